// round 12
// baseline (speedup 1.0000x reference)
#include <cuda_runtime.h>
#include <cuda_fp16.h>
#include <mma.h>
#include <cstdint>
#include <math.h>

using namespace nvcuda;

// Problem constants
#define TSTEPS 512
#define BATCH  512
#define IDIM   128
#define HDIM   512
#define KACT   640   // reordered: cols [0,512)=h, [512,640)=inp

// Partitioning: 8 batch-groups x 16 CTAs = 128 CTAs (1 per SM, one wave)
#define NGROUPS 8
#define GCTAS   16
#define NCTA    (NGROUPS*GCTAS)
#define MB      64
#define HS      32
#define NTHREADS 256   // 8 warps: 2 warp-rows x 4 warp-cols (32x32 gate tiles)

// Extended N: 128 gate cols + 16 fc cols (8 real + 8 zero-pad)
#define NROWS 144

// SMEM padding / tiling
#define WPAD 648      // weight row stride (halfs)
#define GPAD 132      // gates staging row stride (floats)
#define APAD 136      // A-stage row stride (halfs)
#define CHUNK 128     // K columns per staged chunk
#define NCHUNK 5      // 640 / 128
#define HCHUNK 4      // chunks [0,4) = h region [0,512); chunk 4 = inp [512,640)
#define F2P  18       // fcz buffer pitch (floats)

// SMEM layout (bytes):
//  Wsm  144*WPAD*2 = 186624   @ 0        (rows 0..127 gates, 128..143 fc+zeropad)
//  R    max(Ast 2*64*APAD*2=34816, gsm 64*GPAD*4=33792) = 34816 @ 186624 (aliased)
//  fczb 64*F2P*4   = 4608     @ 221440
//  bsm  128*4      = 512      @ 226048
//  fcbs 8*4        = 32       @ 226560
#define SMEM_BYTES 226816

// Global state
__device__ __align__(16) __half g_act[2][BATCH][KACT];   // [parity][row][col]
__device__ unsigned g_bar[NGROUPS];                       // init barrier only
__device__ unsigned g_hflag[NGROUPS*GCTAS];               // h published step-stamps
__device__ unsigned g_iflag[NGROUPS*GCTAS];               // inp published step-stamps

// ---------------- init barrier (one-time) ----------------
__device__ __forceinline__ void bar_arrive(const unsigned* barp) {
    if (threadIdx.x == 0) {
        asm volatile("red.release.gpu.global.add.u32 [%0], %1;"
                     :: "l"(barp), "r"(1u) : "memory");
    }
}
__device__ __forceinline__ void bar_wait(const unsigned* barp, unsigned target) {
    if (threadIdx.x == 0) {
        unsigned v;
        do {
            asm volatile("ld.relaxed.gpu.global.u32 %0, [%1];" : "=r"(v) : "l"(barp));
        } while (v < target);
        asm volatile("fence.acq_rel.gpu;" ::: "memory");
    }
    __syncthreads();
}

// ---------------- fine-grained flags ----------------
__device__ __forceinline__ void flag_publish(unsigned* f, unsigned stamp) {
    asm volatile("st.release.gpu.global.u32 [%0], %1;" :: "l"(f), "r"(stamp) : "memory");
}
__device__ __forceinline__ void poll_ge(const unsigned* f, unsigned stamp) {
    unsigned v;
    do {
        asm volatile("ld.acquire.gpu.global.u32 %0, [%1];" : "=r"(v) : "l"(f) : "memory");
    } while (v < stamp);
}

__device__ __forceinline__ uint4 ldcg4(const void* p) {
    return __ldcg(reinterpret_cast<const uint4*>(p));
}

// Overflow-safe fast sigmoid/tanh (EX2+RCP MUFU path, rel err ~2^-21)
__device__ __forceinline__ float fsigmoid(float z) {
    float e = __expf(-fabsf(z));
    float num = (z >= 0.f) ? 1.f : e;
    return __fdividef(num, 1.f + e);
}
__device__ __forceinline__ float ftanh_(float z) {
    float e = __expf(-2.f * fabsf(z));
    float r = __fdividef(1.f - e, 1.f + e);
    return (z >= 0.f) ? r : -r;
}

// Staged-chunk MMA over chunks [c_begin, c_end). Accumulates act @ W^T.
// 8 warps: warp (wr,wc) owns rows [wr*32,+32) x gate cols [wc*32,+32).
// fc warps additionally accumulate a 16x16 fc band, reusing af[afsel].
// Per-chunk producer polling:
//   mode 0 (h chunks): thread's staged cols come from CTA 4*cc+lseg -> poll 1 flag
//   mode 1 (inp chunk): thread's cols come from CTAs [lseg*4,+4)     -> poll 4 flags
// flags == nullptr -> no polling (prologue).
__device__ __forceinline__ void mma_chunks(
    wmma::fragment<wmma::accumulator, 16, 16, 16, float> (&acc)[2][2],
    wmma::fragment<wmma::accumulator, 16, 16, 16, float>& accfc,
    const __half* __restrict__ gact_p,
    __half* __restrict__ Ast,            // [2 buf][64][APAD]
    const __half* __restrict__ Wsm,
    int row0, int wr, int wc, int lrow, int lseg,
    int c_begin, int c_end, bool do_fc, int afsel,
    const unsigned* flags, unsigned stamp, int inp_mode)
{
    const __half* src = gact_p + (size_t)(row0 + lrow) * KACT + lseg*32;

    if (flags) {
        if (!inp_mode) {
            poll_ge(&flags[c_begin*4 + lseg], stamp);
        } else {
            #pragma unroll
            for (int s = 0; s < 4; s++) poll_ge(&flags[lseg*4 + s], stamp);
        }
    }
    {
        const __half* s = src + c_begin*CHUNK;
        uint4 v0 = ldcg4(s);
        uint4 v1 = ldcg4(s + 8);
        uint4 v2 = ldcg4(s + 16);
        uint4 v3 = ldcg4(s + 24);
        uint4* d = reinterpret_cast<uint4*>(Ast + lrow*APAD + lseg*32);
        d[0] = v0; d[1] = v1; d[2] = v2; d[3] = v3;
    }
    __syncthreads();

    int buf = 0;
    for (int cc = c_begin; cc < c_end; cc++) {
        uint4 p0, p1, p2, p3;
        const bool hn = (cc + 1 < c_end);
        if (hn) {
            if (flags && !inp_mode) poll_ge(&flags[(cc+1)*4 + lseg], stamp);
            const __half* s = src + (cc+1)*CHUNK;
            p0 = ldcg4(s);
            p1 = ldcg4(s + 8);
            p2 = ldcg4(s + 16);
            p3 = ldcg4(s + 24);
        }

        const __half* Ab = Ast + buf * (64 * APAD);
        const int kbase = cc * CHUNK;
        #pragma unroll
        for (int kt = 0; kt < 8; kt++) {
            wmma::fragment<wmma::matrix_a, 16, 16, 16, __half, wmma::row_major> af[2];
            #pragma unroll
            for (int i = 0; i < 2; i++)
                wmma::load_matrix_sync(af[i], Ab + (wr*32 + i*16)*APAD + kt*16, APAD);
            #pragma unroll
            for (int j = 0; j < 2; j++) {
                wmma::fragment<wmma::matrix_b, 16, 16, 16, __half, wmma::col_major> bf;
                wmma::load_matrix_sync(bf, Wsm + (wc*32 + j*16)*WPAD + kbase + kt*16, WPAD);
                #pragma unroll
                for (int i = 0; i < 2; i++)
                    wmma::mma_sync(acc[i][j], af[i], bf, acc[i][j]);
            }
            if (do_fc) {
                wmma::fragment<wmma::matrix_b, 16, 16, 16, __half, wmma::col_major> bffc;
                wmma::load_matrix_sync(bffc, Wsm + 128*WPAD + kbase + kt*16, WPAD);
                wmma::mma_sync(accfc, af[afsel], bffc, accfc);
            }
        }
        if (hn) {
            buf ^= 1;
            uint4* d = reinterpret_cast<uint4*>(Ast + buf*(64*APAD) + lrow*APAD + lseg*32);
            d[0] = p0; d[1] = p1; d[2] = p2; d[3] = p3;
        }
        __syncthreads();
    }
}

__global__ void __launch_bounds__(NTHREADS, 1)
decoder_kernel(
    const float* __restrict__ x,    const float* __restrict__ h0,
    const float* __restrict__ c0,   const float* __restrict__ W_ih,
    const float* __restrict__ W_hh, const float* __restrict__ b_ih,
    const float* __restrict__ b_hh, const float* __restrict__ fc_W,
    const float* __restrict__ fc_b, float* __restrict__ out)
{
    extern __shared__ unsigned char smem_raw[];
    __half* Wsm  = (__half*)smem_raw;                        // [144][WPAD]
    __half* Ast  = (__half*)(smem_raw + 186624);             // R: [2][64][APAD]
    float*  gsm  = (float*)(smem_raw + 186624);              // R: [64][GPAD] (aliased)
    float*  fczb = (float*)(smem_raw + 221440);              // [64][F2P]
    float*  bsm  = (float*)(smem_raw + 226048);              // [128]
    float*  fcbs = (float*)(smem_raw + 226560);              // [8]

    const int tid  = threadIdx.x;
    const int gid  = blockIdx.x / GCTAS;
    const int rk   = blockIdx.x % GCTAS;
    const int row0 = gid * MB;
    const int hs   = rk * HS;
    const unsigned* barp = &g_bar[gid];
    unsigned* hfl = &g_hflag[gid*GCTAS];     // group base
    unsigned* ifl = &g_iflag[gid*GCTAS];

    const int wid = tid >> 5;
    const int wr  = wid >> 2;        // 0..1 : 32 gate rows (batch m) each
    const int wc  = wid & 3;         // 0..3 : 32 gate cols each
    const int lrow = tid >> 2;       // 0..63
    const int lseg = tid & 3;        // 0..3
    // fc spread: wids 1,2,5,6 (one per SMSP). Band b = rows [b*16,+16), af reuse.
    const bool fcw = (wid == 1) || (wid == 2) || (wid == 5) || (wid == 6);
    const int fcband = ((wid >> 2) << 1) | (((wid & 3) == 2) ? 1 : 0);  // 0..3
    const int afsel  = fcband & 1;

    // ---------------- init (once) ----------------
    // Wsm rows 0..127: gates, K-reordered (k<512 -> W_hh, k>=512 -> W_ih)
    // Wsm rows 128..143: fc rows (8 real over K<512, rest zero)
    for (int idx = tid; idx < NROWS*KACT; idx += NTHREADS) {
        int r = idx / KACT, k = idx - r*KACT;
        float v;
        if (r < 128) {
            int q = r >> 5, j = r & 31;
            int grow = q*HDIM + hs + j;
            v = (k < HDIM) ? W_hh[grow*HDIM + k] : W_ih[grow*IDIM + (k - HDIM)];
        } else {
            int ff = r - 128;
            v = (ff < 8 && k < HDIM) ? fc_W[(rk*8 + ff)*HDIM + k] : 0.0f;
        }
        Wsm[r*WPAD + k] = __float2half_rn(v);
    }
    for (int r = tid; r < 128; r += NTHREADS) {
        int q = r >> 5, j = r & 31;
        bsm[r] = b_ih[q*HDIM + hs + j] + b_hh[q*HDIM + hs + j];
    }
    if (tid < 8) fcbs[tid] = fc_b[rk*8 + tid];

    // cell state in registers: element it -> (m = (tid>>5)+it*8, j = tid&31)
    float cr[8];
    #pragma unroll
    for (int it = 0; it < 8; it++) {
        int m = (tid >> 5) + it*8, j = tid & 31;
        cr[it] = c0[(row0+m)*HDIM + hs + j];
    }

    // seed g_act parity 0: h at cols [hs,hs+32), inp at cols [512+rk*8,+8)
    for (int idx = tid; idx < MB*HS; idx += NTHREADS) {
        int m = idx >> 5, j = idx & 31;
        g_act[0][row0+m][hs+j] = __float2half_rn(h0[(row0+m)*HDIM + hs + j]);
    }
    for (int idx = tid; idx < MB*8; idx += NTHREADS) {
        int m = idx >> 3, ccol = rk*8 + (idx & 7);
        g_act[0][row0+m][HDIM+ccol] =
            __float2half_rn(x[(TSTEPS-1)*BATCH*IDIM + (row0+m)*IDIM + ccol]);
    }

    __syncthreads();              // all seed writes done before arrive
    bar_arrive(barp);
    bar_wait(barp, GCTAS);        // seeds visible group-wide

    wmma::fragment<wmma::accumulator, 16, 16, 16, float> acc[2][2];
    wmma::fragment<wmma::accumulator, 16, 16, 16, float> accfc;

    // ---------------- prologue: gates(0) (no fc, no polls) ----------------
    {
        #pragma unroll
        for (int i = 0; i < 2; i++)
            #pragma unroll
            for (int j = 0; j < 2; j++)
                wmma::fill_fragment(acc[i][j], 0.0f);
        mma_chunks(acc, accfc, &g_act[0][0][0], Ast, Wsm, row0, wr, wc, lrow, lseg,
                   0, NCHUNK, false, 0, nullptr, 0, 0);
        #pragma unroll
        for (int i = 0; i < 2; i++)
            #pragma unroll
            for (int j = 0; j < 2; j++)
                wmma::store_matrix_sync(&gsm[(wr*32 + i*16)*GPAD + wc*32 + j*16],
                                        acc[i][j], GPAD, wmma::mem_row_major);
        __syncthreads();
    }

    // ---------------- 512 sequential steps ----------------
    for (int t = 0; t < TSTEPS; t++) {
        const int pw = (t + 1) & 1;      // parity holding h_{t+1} / inp_{t+1}
        const bool more = (t < TSTEPS - 1);
        const unsigned stamp = (unsigned)(t + 1);

        // ===== pointwise LSTM: gsm (gates_t) + cr -> h_{t+1} (global pw) =====
        #pragma unroll
        for (int it = 0; it < 8; it++) {
            int m = (tid >> 5) + it*8, j = tid & 31;
            float zi = gsm[m*GPAD +      j] + bsm[     j];
            float zf = gsm[m*GPAD + 32 + j] + bsm[32 + j];
            float zg = gsm[m*GPAD + 64 + j] + bsm[64 + j];
            float zo = gsm[m*GPAD + 96 + j] + bsm[96 + j];
            float ig = fsigmoid(zi);
            float fg = fsigmoid(zf);
            float gg = ftanh_(zg);
            float og = fsigmoid(zo);
            float cn = fg*cr[it] + ig*gg;
            float hn = og * ftanh_(cn);
            cr[it] = cn;
            g_act[pw][row0+m][hs+j] = __float2half_rn(hn);
        }
        __syncthreads();                          // all h writes done
        if (tid == 0) flag_publish(&hfl[rk], stamp);

        // ===== phase1: gates(t+1) h-part + fcz_t (fc on 4 warps), chunk-pipelined polls =====
        #pragma unroll
        for (int i = 0; i < 2; i++)
            #pragma unroll
            for (int j = 0; j < 2; j++)
                wmma::fill_fragment(acc[i][j], 0.0f);
        wmma::fill_fragment(accfc, 0.0f);
        mma_chunks(acc, accfc, &g_act[pw][0][0], Ast, Wsm, row0, wr, wc, lrow, lseg,
                   0, HCHUNK, fcw, afsel, hfl, stamp, 0);
        if (fcw)
            wmma::store_matrix_sync(&fczb[fcband*16*F2P], accfc, F2P, wmma::mem_row_major);
        __syncthreads();

        // ===== finalize: out_t = tanh(0.5*(fcz+b)); feedback inp_{t+1} =====
        float yv[2]; int mv[2], nv[2];
        #pragma unroll
        for (int it = 0; it < 2; it++) {
            int idx = tid + it*NTHREADS;
            int m = idx >> 3, ff = idx & 7;
            float z = fczb[m*F2P + ff] + fcbs[ff];
            float y = ftanh_(0.5f * z);
            g_act[pw][row0+m][HDIM + rk*8 + ff] = __float2half_rn(y);
            yv[it] = y; mv[it] = m; nv[it] = rk*8 + ff;
        }
        __syncthreads();                          // all inp writes done
        if (tid == 0) flag_publish(&ifl[rk], stamp);

        // out stores overlap the inp-flag propagation window
        #pragma unroll
        for (int it = 0; it < 2; it++)
            out[(TSTEPS-1-t)*BATCH*IDIM + (row0+mv[it])*IDIM + nv[it]] = yv[it];

        if (more) {
            // ===== phase2: gates(t+1) inp-part (polls 4 inp producers); publish gsm =====
            mma_chunks(acc, accfc, &g_act[pw][0][0], Ast, Wsm, row0, wr, wc, lrow, lseg,
                       HCHUNK, NCHUNK, false, 0, ifl, stamp, 1);
            #pragma unroll
            for (int i = 0; i < 2; i++)
                #pragma unroll
                for (int j = 0; j < 2; j++)
                    wmma::store_matrix_sync(&gsm[(wr*32 + i*16)*GPAD + wc*32 + j*16],
                                            acc[i][j], GPAD, wmma::mem_row_major);
            __syncthreads();
        }
    }
}

extern "C" void kernel_launch(void* const* d_in, const int* in_sizes, int n_in,
                              void* d_out, int out_size)
{
    const float* x    = (const float*)d_in[0];
    // d_in[1] = enc_hiddens : unused by the reference recursion
    const float* h0   = (const float*)d_in[2];
    const float* c0   = (const float*)d_in[3];
    const float* W_ih = (const float*)d_in[4];
    const float* W_hh = (const float*)d_in[5];
    const float* b_ih = (const float*)d_in[6];
    const float* b_hh = (const float*)d_in[7];
    const float* fc_W = (const float*)d_in[8];
    const float* fc_b = (const float*)d_in[9];
    float* out = (float*)d_out;

    cudaFuncSetAttribute(decoder_kernel, cudaFuncAttributeMaxDynamicSharedMemorySize, SMEM_BYTES);

    // Reset barrier + flag state every replay (captured memset nodes)
    void* p = nullptr;
    cudaGetSymbolAddress(&p, g_bar);
    cudaMemsetAsync(p, 0, sizeof(unsigned) * NGROUPS);
    cudaGetSymbolAddress(&p, g_hflag);
    cudaMemsetAsync(p, 0, sizeof(unsigned) * NGROUPS * GCTAS);
    cudaGetSymbolAddress(&p, g_iflag);
    cudaMemsetAsync(p, 0, sizeof(unsigned) * NGROUPS * GCTAS);

    decoder_kernel<<<NCTA, NTHREADS, SMEM_BYTES>>>(x, h0, c0, W_ih, W_hh,
                                                   b_ih, b_hh, fc_W, fc_b, out);
}

// round 13
// speedup vs baseline: 1.7771x; 1.7771x over previous
#include <cuda_runtime.h>
#include <cuda_fp16.h>
#include <mma.h>
#include <cstdint>
#include <math.h>

using namespace nvcuda;

// Problem constants
#define TSTEPS 512
#define BATCH  512
#define IDIM   128
#define HDIM   512
#define KACT   640   // reordered: cols [0,512)=h, [512,640)=inp

// Partitioning: 8 batch-groups x 16 CTAs = 128 CTAs (1 per SM, one wave)
#define NGROUPS 8
#define GCTAS   16
#define NCTA    (NGROUPS*GCTAS)
#define MB      64
#define HS      32
#define NTHREADS 256   // 8 warps: 2 warp-rows x 4 warp-cols (32x32 gate tiles)

// Extended N: 128 gate cols + 16 fc cols (8 real + 8 zero-pad)
#define NROWS 144

// SMEM padding / tiling
#define WPAD 648      // weight row stride (halfs)
#define GPAD 132      // gates staging row stride (floats)
#define APAD 136      // A-stage row stride (halfs)
#define CHUNK 128     // K columns per staged chunk
#define NCHUNK 5      // 640 / 128
#define HCHUNK 4      // chunks [0,4) = h region [0,512); chunk 4 = inp [512,640)
#define F2P  18       // fcz buffer pitch (floats)

// SMEM layout (bytes):
//  Wsm  144*WPAD*2 = 186624   @ 0        (rows 0..127 gates, 128..143 fc+zeropad)
//  R    max(Ast 2*64*APAD*2=34816, gsm 64*GPAD*4=33792) = 34816 @ 186624 (aliased)
//  fczb 64*F2P*4   = 4608     @ 221440
//  bsm  128*4      = 512      @ 226048
//  fcbs 8*4        = 32       @ 226560
#define SMEM_BYTES 226816

// Global state
__device__ __align__(16) __half g_act[2][BATCH][KACT];   // [parity][row][col]
__device__ unsigned g_bar[NGROUPS];                       // one-time init barrier
__device__ unsigned g_barh[NGROUPS*4];                    // sub-barriers: h quarter q (CTAs 4q..4q+3)
__device__ unsigned g_bari[NGROUPS];                      // inp barrier (monotonic)

// ---------------- sync primitives (thread-0-only polling) ----------------
__device__ __forceinline__ void ctr_arrive(const unsigned* p) {
    asm volatile("red.release.gpu.global.add.u32 [%0], %1;" :: "l"(p), "r"(1u) : "memory");
}
// poll by CALLER-GUARANTEED single thread; acquire semantics via trailing fence
__device__ __forceinline__ void ctr_poll(const unsigned* p, unsigned target) {
    unsigned v;
    do {
        asm volatile("ld.relaxed.gpu.global.u32 %0, [%1];" : "=r"(v) : "l"(p));
    } while (v < target);
    asm volatile("fence.acq_rel.gpu;" ::: "memory");
}

__device__ __forceinline__ uint4 ldcg4(const void* p) {
    return __ldcg(reinterpret_cast<const uint4*>(p));
}

// Overflow-safe fast sigmoid/tanh (EX2+RCP MUFU path, rel err ~2^-21)
__device__ __forceinline__ float fsigmoid(float z) {
    float e = __expf(-fabsf(z));
    float num = (z >= 0.f) ? 1.f : e;
    return __fdividef(num, 1.f + e);
}
__device__ __forceinline__ float ftanh_(float z) {
    float e = __expf(-2.f * fabsf(z));
    float r = __fdividef(1.f - e, 1.f + e);
    return (z >= 0.f) ? r : -r;
}

// Staged-chunk MMA over chunks [c_begin, c_end). Accumulates act @ W^T.
// 8 warps: warp (wr,wc) owns rows [wr*32,+32) x gate cols [wc*32,+32).
// fc warps (one per SMSP) each accumulate a 16x16 fc band reusing af[afsel].
// hbar != nullptr: sub-barrier poll (thread 0 only) gates each chunk's staging;
// chunk cc's h-cols are produced exactly by the CTAs of counter cc.
__device__ __forceinline__ void mma_chunks(
    wmma::fragment<wmma::accumulator, 16, 16, 16, float> (&acc)[2][2],
    wmma::fragment<wmma::accumulator, 16, 16, 16, float>& accfc,
    const __half* __restrict__ gact_p,
    __half* __restrict__ Ast,            // [2 buf][64][APAD]
    const __half* __restrict__ Wsm,
    int row0, int wr, int wc, int lrow, int lseg,
    int c_begin, int c_end, bool do_fc, int afsel,
    const unsigned* hbar, unsigned tgt4)
{
    const __half* src = gact_p + (size_t)(row0 + lrow) * KACT + lseg*32;
    const int tid = threadIdx.x;

    if (hbar) {
        if (tid == 0) ctr_poll(&hbar[c_begin], tgt4);
        __syncthreads();                  // gate staging loads on poll
    }
    {
        const __half* s = src + c_begin*CHUNK;
        uint4 v0 = ldcg4(s);
        uint4 v1 = ldcg4(s + 8);
        uint4 v2 = ldcg4(s + 16);
        uint4 v3 = ldcg4(s + 24);
        uint4* d = reinterpret_cast<uint4*>(Ast + lrow*APAD + lseg*32);
        d[0] = v0; d[1] = v1; d[2] = v2; d[3] = v3;
    }
    __syncthreads();

    int buf = 0;
    for (int cc = c_begin; cc < c_end; cc++) {
        uint4 p0, p1, p2, p3;
        const bool hn = (cc + 1 < c_end);
        if (hn) {
            if (hbar) {
                if (tid == 0) ctr_poll(&hbar[cc+1], tgt4);
                __syncthreads();          // gate prefetch on poll
            }
            const __half* s = src + (cc+1)*CHUNK;
            p0 = ldcg4(s);
            p1 = ldcg4(s + 8);
            p2 = ldcg4(s + 16);
            p3 = ldcg4(s + 24);
        }

        const __half* Ab = Ast + buf * (64 * APAD);
        const int kbase = cc * CHUNK;
        #pragma unroll
        for (int kt = 0; kt < 8; kt++) {
            wmma::fragment<wmma::matrix_a, 16, 16, 16, __half, wmma::row_major> af[2];
            #pragma unroll
            for (int i = 0; i < 2; i++)
                wmma::load_matrix_sync(af[i], Ab + (wr*32 + i*16)*APAD + kt*16, APAD);
            #pragma unroll
            for (int j = 0; j < 2; j++) {
                wmma::fragment<wmma::matrix_b, 16, 16, 16, __half, wmma::col_major> bf;
                wmma::load_matrix_sync(bf, Wsm + (wc*32 + j*16)*WPAD + kbase + kt*16, WPAD);
                #pragma unroll
                for (int i = 0; i < 2; i++)
                    wmma::mma_sync(acc[i][j], af[i], bf, acc[i][j]);
            }
            if (do_fc) {
                wmma::fragment<wmma::matrix_b, 16, 16, 16, __half, wmma::col_major> bffc;
                wmma::load_matrix_sync(bffc, Wsm + 128*WPAD + kbase + kt*16, WPAD);
                wmma::mma_sync(accfc, af[afsel], bffc, accfc);
            }
        }
        if (hn) {
            buf ^= 1;
            uint4* d = reinterpret_cast<uint4*>(Ast + buf*(64*APAD) + lrow*APAD + lseg*32);
            d[0] = p0; d[1] = p1; d[2] = p2; d[3] = p3;
        }
        __syncthreads();
    }
}

__global__ void __launch_bounds__(NTHREADS, 1)
decoder_kernel(
    const float* __restrict__ x,    const float* __restrict__ h0,
    const float* __restrict__ c0,   const float* __restrict__ W_ih,
    const float* __restrict__ W_hh, const float* __restrict__ b_ih,
    const float* __restrict__ b_hh, const float* __restrict__ fc_W,
    const float* __restrict__ fc_b, float* __restrict__ out)
{
    extern __shared__ unsigned char smem_raw[];
    __half* Wsm  = (__half*)smem_raw;                        // [144][WPAD]
    __half* Ast  = (__half*)(smem_raw + 186624);             // R: [2][64][APAD]
    float*  gsm  = (float*)(smem_raw + 186624);              // R: [64][GPAD] (aliased)
    float*  fczb = (float*)(smem_raw + 221440);              // [64][F2P]
    float*  bsm  = (float*)(smem_raw + 226048);              // [128]
    float*  fcbs = (float*)(smem_raw + 226560);              // [8]

    const int tid  = threadIdx.x;
    const int gid  = blockIdx.x / GCTAS;
    const int rk   = blockIdx.x % GCTAS;
    const int row0 = gid * MB;
    const int hs   = rk * HS;
    const unsigned* hbar = &g_barh[gid*4];
    const unsigned* ibar = &g_bari[gid];

    const int wid = tid >> 5;
    const int wr  = wid >> 2;        // 0..1 : 32 gate rows (batch m) each
    const int wc  = wid & 3;         // 0..3 : 32 gate cols each
    const int lrow = tid >> 2;       // 0..63
    const int lseg = tid & 3;        // 0..3
    // fc spread: wids 1,2,5,6 (one per SMSP). Band fcband = rows [fcband*16,+16).
    const bool fcw = (wid == 1) || (wid == 2) || (wid == 5) || (wid == 6);
    const int fcband = ((wid >> 2) << 1) | (((wid & 3) == 2) ? 1 : 0);  // 0..3
    const int afsel  = fcband & 1;

    // ---------------- init (once) ----------------
    // Wsm rows 0..127: gates, K-reordered (k<512 -> W_hh, k>=512 -> W_ih)
    // Wsm rows 128..143: fc rows (8 real over K<512, rest zero)
    for (int idx = tid; idx < NROWS*KACT; idx += NTHREADS) {
        int r = idx / KACT, k = idx - r*KACT;
        float v;
        if (r < 128) {
            int q = r >> 5, j = r & 31;
            int grow = q*HDIM + hs + j;
            v = (k < HDIM) ? W_hh[grow*HDIM + k] : W_ih[grow*IDIM + (k - HDIM)];
        } else {
            int ff = r - 128;
            v = (ff < 8 && k < HDIM) ? fc_W[(rk*8 + ff)*HDIM + k] : 0.0f;
        }
        Wsm[r*WPAD + k] = __float2half_rn(v);
    }
    for (int r = tid; r < 128; r += NTHREADS) {
        int q = r >> 5, j = r & 31;
        bsm[r] = b_ih[q*HDIM + hs + j] + b_hh[q*HDIM + hs + j];
    }
    if (tid < 8) fcbs[tid] = fc_b[rk*8 + tid];

    // cell state in registers: element it -> (m = (tid>>5)+it*8, j = tid&31)
    float cr[8];
    #pragma unroll
    for (int it = 0; it < 8; it++) {
        int m = (tid >> 5) + it*8, j = tid & 31;
        cr[it] = c0[(row0+m)*HDIM + hs + j];
    }

    // seed g_act parity 0: h at cols [hs,hs+32), inp at cols [512+rk*8,+8)
    for (int idx = tid; idx < MB*HS; idx += NTHREADS) {
        int m = idx >> 5, j = idx & 31;
        g_act[0][row0+m][hs+j] = __float2half_rn(h0[(row0+m)*HDIM + hs + j]);
    }
    for (int idx = tid; idx < MB*8; idx += NTHREADS) {
        int m = idx >> 3, ccol = rk*8 + (idx & 7);
        g_act[0][row0+m][HDIM+ccol] =
            __float2half_rn(x[(TSTEPS-1)*BATCH*IDIM + (row0+m)*IDIM + ccol]);
    }

    // one-time init barrier: all seeds visible group-wide
    __syncthreads();
    if (tid == 0) {
        ctr_arrive(&g_bar[gid]);
        ctr_poll(&g_bar[gid], GCTAS);
    }
    __syncthreads();

    wmma::fragment<wmma::accumulator, 16, 16, 16, float> acc[2][2];
    wmma::fragment<wmma::accumulator, 16, 16, 16, float> accfc;

    // ---------------- prologue: gates(0) (no fc, no polls) ----------------
    {
        #pragma unroll
        for (int i = 0; i < 2; i++)
            #pragma unroll
            for (int j = 0; j < 2; j++)
                wmma::fill_fragment(acc[i][j], 0.0f);
        mma_chunks(acc, accfc, &g_act[0][0][0], Ast, Wsm, row0, wr, wc, lrow, lseg,
                   0, NCHUNK, false, 0, nullptr, 0);
        #pragma unroll
        for (int i = 0; i < 2; i++)
            #pragma unroll
            for (int j = 0; j < 2; j++)
                wmma::store_matrix_sync(&gsm[(wr*32 + i*16)*GPAD + wc*32 + j*16],
                                        acc[i][j], GPAD, wmma::mem_row_major);
        __syncthreads();
    }

    // ---------------- 512 sequential steps ----------------
    for (int t = 0; t < TSTEPS; t++) {
        const int pw = (t + 1) & 1;      // parity holding h_{t+1} / inp_{t+1}
        const bool more = (t < TSTEPS - 1);
        const unsigned stamp = (unsigned)(t + 1);

        // ===== pointwise LSTM: gsm (gates_t) + cr -> h_{t+1} (global pw) =====
        #pragma unroll
        for (int it = 0; it < 8; it++) {
            int m = (tid >> 5) + it*8, j = tid & 31;
            float zi = gsm[m*GPAD +      j] + bsm[     j];
            float zf = gsm[m*GPAD + 32 + j] + bsm[32 + j];
            float zg = gsm[m*GPAD + 64 + j] + bsm[64 + j];
            float zo = gsm[m*GPAD + 96 + j] + bsm[96 + j];
            float ig = fsigmoid(zi);
            float fg = fsigmoid(zf);
            float gg = ftanh_(zg);
            float og = fsigmoid(zo);
            float cn = fg*cr[it] + ig*gg;
            float hn = og * ftanh_(cn);
            cr[it] = cn;
            g_act[pw][row0+m][hs+j] = __float2half_rn(hn);
        }
        __syncthreads();                           // all h writes done
        if (tid == 0) ctr_arrive(&hbar[rk >> 2]);  // quarter sub-barrier arrive

        // ===== phase1: gates(t+1) h-part + fcz_t, chunk-pipelined sub-barrier polls =====
        #pragma unroll
        for (int i = 0; i < 2; i++)
            #pragma unroll
            for (int j = 0; j < 2; j++)
                wmma::fill_fragment(acc[i][j], 0.0f);
        wmma::fill_fragment(accfc, 0.0f);
        mma_chunks(acc, accfc, &g_act[pw][0][0], Ast, Wsm, row0, wr, wc, lrow, lseg,
                   0, HCHUNK, fcw, afsel, hbar, 4u*stamp);
        if (fcw)
            wmma::store_matrix_sync(&fczb[fcband*16*F2P], accfc, F2P, wmma::mem_row_major);
        __syncthreads();

        // ===== finalize: out_t = tanh(0.5*(fcz+b)); feedback inp_{t+1} =====
        float yv[2]; int mv[2], nv[2];
        #pragma unroll
        for (int it = 0; it < 2; it++) {
            int idx = tid + it*NTHREADS;
            int m = idx >> 3, ff = idx & 7;
            float z = fczb[m*F2P + ff] + fcbs[ff];
            float y = ftanh_(0.5f * z);
            g_act[pw][row0+m][HDIM + rk*8 + ff] = __float2half_rn(y);
            yv[it] = y; mv[it] = m; nv[it] = rk*8 + ff;
        }
        __syncthreads();                           // all inp writes done
        if (tid == 0) ctr_arrive(ibar);            // B arrive

        // out stores overlap the barrier-B window
        #pragma unroll
        for (int it = 0; it < 2; it++)
            out[(TSTEPS-1-t)*BATCH*IDIM + (row0+mv[it])*IDIM + nv[it]] = yv[it];

        if (more) {
            // ===== barrier B wait, then phase2: gates(t+1) inp-part; publish gsm =====
            if (tid == 0) ctr_poll(ibar, (unsigned)GCTAS * stamp);
            __syncthreads();
            mma_chunks(acc, accfc, &g_act[pw][0][0], Ast, Wsm, row0, wr, wc, lrow, lseg,
                       HCHUNK, NCHUNK, false, 0, nullptr, 0);
            #pragma unroll
            for (int i = 0; i < 2; i++)
                #pragma unroll
                for (int j = 0; j < 2; j++)
                    wmma::store_matrix_sync(&gsm[(wr*32 + i*16)*GPAD + wc*32 + j*16],
                                            acc[i][j], GPAD, wmma::mem_row_major);
            __syncthreads();
        }
    }
}

extern "C" void kernel_launch(void* const* d_in, const int* in_sizes, int n_in,
                              void* d_out, int out_size)
{
    const float* x    = (const float*)d_in[0];
    // d_in[1] = enc_hiddens : unused by the reference recursion
    const float* h0   = (const float*)d_in[2];
    const float* c0   = (const float*)d_in[3];
    const float* W_ih = (const float*)d_in[4];
    const float* W_hh = (const float*)d_in[5];
    const float* b_ih = (const float*)d_in[6];
    const float* b_hh = (const float*)d_in[7];
    const float* fc_W = (const float*)d_in[8];
    const float* fc_b = (const float*)d_in[9];
    float* out = (float*)d_out;

    cudaFuncSetAttribute(decoder_kernel, cudaFuncAttributeMaxDynamicSharedMemorySize, SMEM_BYTES);

    // Reset barrier/flag counters every replay (captured memset nodes)
    void* p = nullptr;
    cudaGetSymbolAddress(&p, g_bar);
    cudaMemsetAsync(p, 0, sizeof(unsigned) * NGROUPS);
    cudaGetSymbolAddress(&p, g_barh);
    cudaMemsetAsync(p, 0, sizeof(unsigned) * NGROUPS * 4);
    cudaGetSymbolAddress(&p, g_bari);
    cudaMemsetAsync(p, 0, sizeof(unsigned) * NGROUPS);

    decoder_kernel<<<NCTA, NTHREADS, SMEM_BYTES>>>(x, h0, c0, W_ih, W_hh,
                                                   b_ih, b_hh, fc_W, fc_b, out);
}

// round 14
// speedup vs baseline: 2.0544x; 1.1561x over previous
#include <cuda_runtime.h>
#include <cuda_fp16.h>
#include <mma.h>
#include <cstdint>
#include <math.h>

using namespace nvcuda;

// Problem constants
#define TSTEPS 512
#define BATCH  512
#define IDIM   128
#define HDIM   512
#define KACT   640   // reordered: cols [0,512)=h, [512,640)=inp

// Partitioning: 8 batch-groups x 16 CTAs = 128 CTAs (1 per SM, one wave)
#define NGROUPS 8
#define GCTAS   16
#define NCTA    (NGROUPS*GCTAS)
#define MB      64
#define HS      32
#define NTHREADS 256   // 8 warps: 2 warp-rows x 4 warp-cols (32x32 gate tiles)

// Extended N: 128 gate cols + 16 fc cols (8 real + 8 zero-pad)
#define NROWS 144

// SMEM padding / tiling
#define WPAD 648      // weight row stride (halfs)
#define GPAD 132      // gates staging row stride (floats)
#define APAD 136      // A-stage row stride (halfs); 272B rows (16B aligned)
#define CHUNK 128     // K columns per staged chunk
#define NCHUNK 5      // 640 / 128
#define HCHUNK 4      // chunks [0,4) = h region [0,512); chunk 4 = inp [512,640)
#define F2P  18       // fcz buffer pitch (floats)

// SMEM layout (bytes):
//  Wsm  144*WPAD*2 = 186624   @ 0        (rows 0..127 gates, 128..143 fc+zeropad)
//  R    max(Ast 2*64*APAD*2=34816, gsm 64*GPAD*4=33792) = 34816 @ 186624 (aliased)
//  fczb 64*F2P*4   = 4608     @ 221440
//  bsm  128*4      = 512      @ 226048
//  fcbs 8*4        = 32       @ 226560
#define SMEM_BYTES 226816

// Global state
__device__ __align__(16) __half g_act[2][BATCH][KACT];   // [parity][row][col]
__device__ unsigned g_bar[NGROUPS];                       // monotonic barrier counters

// ---------------- barriers (release-atomic + relaxed spin, tid0 only) ----------------
__device__ __forceinline__ void bar_arrive(const unsigned* barp) {
    if (threadIdx.x == 0) {
        asm volatile("red.release.gpu.global.add.u32 [%0], %1;"
                     :: "l"(barp), "r"(1u) : "memory");
    }
}
__device__ __forceinline__ void bar_wait(const unsigned* barp, unsigned target) {
    if (threadIdx.x == 0) {
        unsigned v;
        do {
            asm volatile("ld.relaxed.gpu.global.u32 %0, [%1];" : "=r"(v) : "l"(barp));
        } while (v < target);
        asm volatile("fence.acq_rel.gpu;" ::: "memory");
    }
    __syncthreads();
}

// ---------------- cp.async staging ----------------
__device__ __forceinline__ uint32_t smem_u32(const void* p) {
    uint32_t a;
    asm("{ .reg .u64 t; cvta.to.shared.u64 t, %1; cvt.u32.u64 %0, t; }" : "=r"(a) : "l"(p));
    return a;
}
__device__ __forceinline__ void cp16(uint32_t dst, const void* src) {
    asm volatile("cp.async.cg.shared.global [%0], [%1], 16;" :: "r"(dst), "l"(src) : "memory");
}
#define CP_COMMIT() asm volatile("cp.async.commit_group;" ::: "memory")
#define CP_WAIT0()  asm volatile("cp.async.wait_group 0;" ::: "memory")

// Overflow-safe fast sigmoid/tanh (EX2+RCP MUFU path, rel err ~2^-21)
__device__ __forceinline__ float fsigmoid(float z) {
    float e = __expf(-fabsf(z));
    float num = (z >= 0.f) ? 1.f : e;
    return __fdividef(num, 1.f + e);
}
__device__ __forceinline__ float ftanh_(float z) {
    float e = __expf(-2.f * fabsf(z));
    float r = __fdividef(1.f - e, 1.f + e);
    return (z >= 0.f) ? r : -r;
}

// Staged-chunk MMA over chunks [c_begin, c_end). Accumulates act @ W^T.
// 8 warps: warp (wr,wc) owns rows [wr*32,+32) x gate cols [wc*32,+32).
// fc warps (wids 0,1,6,7; one per SMSP) each accumulate one 16x16 fc band,
// reusing the A fragment af[afsel] they already loaded.
// Staging via cp.async: next chunk's copy is issued BEFORE the MMA and waited
// after it, so the global->SMEM transfer overlaps the tensor work.
__device__ __forceinline__ void mma_chunks(
    wmma::fragment<wmma::accumulator, 16, 16, 16, float> (&acc)[2][2],
    wmma::fragment<wmma::accumulator, 16, 16, 16, float>& accfc,
    const __half* __restrict__ gact_p,
    __half* __restrict__ Ast,            // [2 buf][64][APAD]
    const __half* __restrict__ Wsm,
    int row0, int wr, int wc, int lrow, int lseg,
    int c_begin, int c_end, bool do_fc, int afsel)
{
    const __half* src = gact_p + (size_t)(row0 + lrow) * KACT + lseg*32;
    const uint32_t dstb = smem_u32(Ast) + (uint32_t)(lrow*APAD + lseg*32) * 2;
    const uint32_t bufstride = (uint32_t)(64*APAD) * 2;

    // stage chunk c_begin into buf 0
    {
        const __half* s = src + c_begin*CHUNK;
        cp16(dstb,      s);
        cp16(dstb + 16, s + 8);
        cp16(dstb + 32, s + 16);
        cp16(dstb + 48, s + 24);
        CP_COMMIT(); CP_WAIT0();
    }
    __syncthreads();

    int buf = 0;
    for (int cc = c_begin; cc < c_end; cc++) {
        const bool hn = (cc + 1 < c_end);
        if (hn) {
            const __half* s = src + (cc+1)*CHUNK;
            uint32_t d = dstb + (uint32_t)(buf ^ 1) * bufstride;
            cp16(d,      s);
            cp16(d + 16, s + 8);
            cp16(d + 32, s + 16);
            cp16(d + 48, s + 24);
            CP_COMMIT();
        }

        const __half* Ab = Ast + buf * (64 * APAD);
        const int kbase = cc * CHUNK;
        #pragma unroll
        for (int kt = 0; kt < 8; kt++) {
            wmma::fragment<wmma::matrix_a, 16, 16, 16, __half, wmma::row_major> af[2];
            #pragma unroll
            for (int i = 0; i < 2; i++)
                wmma::load_matrix_sync(af[i], Ab + (wr*32 + i*16)*APAD + kt*16, APAD);
            #pragma unroll
            for (int j = 0; j < 2; j++) {
                wmma::fragment<wmma::matrix_b, 16, 16, 16, __half, wmma::col_major> bf;
                wmma::load_matrix_sync(bf, Wsm + (wc*32 + j*16)*WPAD + kbase + kt*16, WPAD);
                #pragma unroll
                for (int i = 0; i < 2; i++)
                    wmma::mma_sync(acc[i][j], af[i], bf, acc[i][j]);
            }
            if (do_fc) {
                wmma::fragment<wmma::matrix_b, 16, 16, 16, __half, wmma::col_major> bffc;
                wmma::load_matrix_sync(bffc, Wsm + 128*WPAD + kbase + kt*16, WPAD);
                wmma::mma_sync(accfc, af[afsel], bffc, accfc);
            }
        }
        if (hn) { buf ^= 1; CP_WAIT0(); }
        __syncthreads();
    }
}

__global__ void __launch_bounds__(NTHREADS, 1)
decoder_kernel(
    const float* __restrict__ x,    const float* __restrict__ h0,
    const float* __restrict__ c0,   const float* __restrict__ W_ih,
    const float* __restrict__ W_hh, const float* __restrict__ b_ih,
    const float* __restrict__ b_hh, const float* __restrict__ fc_W,
    const float* __restrict__ fc_b, float* __restrict__ out)
{
    extern __shared__ unsigned char smem_raw[];
    __half* Wsm  = (__half*)smem_raw;                        // [144][WPAD]
    __half* Ast  = (__half*)(smem_raw + 186624);             // R: [2][64][APAD]
    float*  gsm  = (float*)(smem_raw + 186624);              // R: [64][GPAD] (aliased)
    float*  fczb = (float*)(smem_raw + 221440);              // [64][F2P]
    float*  bsm  = (float*)(smem_raw + 226048);              // [128]
    float*  fcbs = (float*)(smem_raw + 226560);              // [8]

    const int tid  = threadIdx.x;
    const int gid  = blockIdx.x / GCTAS;
    const int rk   = blockIdx.x % GCTAS;
    const int row0 = gid * MB;
    const int hs   = rk * HS;
    const unsigned* barp = &g_bar[gid];

    const int wid = tid >> 5;
    const int wr  = wid >> 2;        // 0..1 : 32 gate rows (batch m) each
    const int wc  = wid & 3;         // 0..3 : 32 gate cols each
    const int lrow = tid >> 2;       // 0..63
    const int lseg = tid & 3;        // 0..3
    // fc spread: wids 0,1 (wr0, SMSP0/1) and 6,7 (wr1, SMSP2/3); one band each.
    const bool fcw = (wid == 0) || (wid == 1) || (wid == 6) || (wid == 7);
    const int fcband = (wid >= 4) ? (wid - 4) : wid;   // 0,1,2,3
    const int afsel  = fcband & 1;

    // ---------------- init (once) ----------------
    // Wsm rows 0..127: gates, K-reordered (k<512 -> W_hh, k>=512 -> W_ih)
    // Wsm rows 128..143: fc rows (8 real over K<512, rest zero)
    for (int idx = tid; idx < NROWS*KACT; idx += NTHREADS) {
        int r = idx / KACT, k = idx - r*KACT;
        float v;
        if (r < 128) {
            int q = r >> 5, j = r & 31;
            int grow = q*HDIM + hs + j;
            v = (k < HDIM) ? W_hh[grow*HDIM + k] : W_ih[grow*IDIM + (k - HDIM)];
        } else {
            int ff = r - 128;
            v = (ff < 8 && k < HDIM) ? fc_W[(rk*8 + ff)*HDIM + k] : 0.0f;
        }
        Wsm[r*WPAD + k] = __float2half_rn(v);
    }
    for (int r = tid; r < 128; r += NTHREADS) {
        int q = r >> 5, j = r & 31;
        bsm[r] = b_ih[q*HDIM + hs + j] + b_hh[q*HDIM + hs + j];
    }
    if (tid < 8) fcbs[tid] = fc_b[rk*8 + tid];

    // cell state in registers: element it -> (m = (tid>>5)+it*8, j = tid&31)
    float cr[8];
    #pragma unroll
    for (int it = 0; it < 8; it++) {
        int m = (tid >> 5) + it*8, j = tid & 31;
        cr[it] = c0[(row0+m)*HDIM + hs + j];
    }

    // seed g_act parity 0: h at cols [hs,hs+32), inp at cols [512+rk*8,+8)
    for (int idx = tid; idx < MB*HS; idx += NTHREADS) {
        int m = idx >> 5, j = idx & 31;
        g_act[0][row0+m][hs+j] = __float2half_rn(h0[(row0+m)*HDIM + hs + j]);
    }
    for (int idx = tid; idx < MB*8; idx += NTHREADS) {
        int m = idx >> 3, ccol = rk*8 + (idx & 7);
        g_act[0][row0+m][HDIM+ccol] =
            __float2half_rn(x[(TSTEPS-1)*BATCH*IDIM + (row0+m)*IDIM + ccol]);
    }

    __syncthreads();              // all seed writes done before arrive
    bar_arrive(barp);
    unsigned tgt = GCTAS;
    bar_wait(barp, tgt);          // seeds visible group-wide

    wmma::fragment<wmma::accumulator, 16, 16, 16, float> acc[2][2];
    wmma::fragment<wmma::accumulator, 16, 16, 16, float> accfc;

    // ---------------- prologue: gates(0) (no fc) ----------------
    {
        #pragma unroll
        for (int i = 0; i < 2; i++)
            #pragma unroll
            for (int j = 0; j < 2; j++)
                wmma::fill_fragment(acc[i][j], 0.0f);
        mma_chunks(acc, accfc, &g_act[0][0][0], Ast, Wsm, row0, wr, wc, lrow, lseg,
                   0, NCHUNK, false, 0);
        #pragma unroll
        for (int i = 0; i < 2; i++)
            #pragma unroll
            for (int j = 0; j < 2; j++)
                wmma::store_matrix_sync(&gsm[(wr*32 + i*16)*GPAD + wc*32 + j*16],
                                        acc[i][j], GPAD, wmma::mem_row_major);
        __syncthreads();
    }

    // ---------------- 512 sequential steps ----------------
    for (int t = 0; t < TSTEPS; t++) {
        const int pw = (t + 1) & 1;      // parity holding h_{t+1} / inp_{t+1}
        const bool more = (t < TSTEPS - 1);

        // ===== pointwise LSTM: gsm (gates_t) + cr -> h_{t+1} (global pw) =====
        #pragma unroll
        for (int it = 0; it < 8; it++) {
            int m = (tid >> 5) + it*8, j = tid & 31;
            float zi = gsm[m*GPAD +      j] + bsm[     j];
            float zf = gsm[m*GPAD + 32 + j] + bsm[32 + j];
            float zg = gsm[m*GPAD + 64 + j] + bsm[64 + j];
            float zo = gsm[m*GPAD + 96 + j] + bsm[96 + j];
            float ig = fsigmoid(zi);
            float fg = fsigmoid(zf);
            float gg = ftanh_(zg);
            float og = fsigmoid(zo);
            float cn = fg*cr[it] + ig*gg;
            float hn = og * ftanh_(cn);
            cr[it] = cn;
            g_act[pw][row0+m][hs+j] = __float2half_rn(hn);
        }
        __syncthreads();                 // all h writes done before arrive
        bar_arrive(barp);                // A: h_{t+1} published
        tgt += GCTAS;
        bar_wait(barp, tgt);

        // ===== phase1: gates(t+1) h-part + FULL fcz_t (fc on 4 warps) =====
        #pragma unroll
        for (int i = 0; i < 2; i++)
            #pragma unroll
            for (int j = 0; j < 2; j++)
                wmma::fill_fragment(acc[i][j], 0.0f);
        wmma::fill_fragment(accfc, 0.0f);
        mma_chunks(acc, accfc, &g_act[pw][0][0], Ast, Wsm, row0, wr, wc, lrow, lseg,
                   0, HCHUNK, fcw, afsel);
        if (fcw)
            wmma::store_matrix_sync(&fczb[fcband*16*F2P], accfc, F2P, wmma::mem_row_major);
        __syncthreads();

        // ===== finalize: out_t = tanh(0.5*(fcz+b)); feedback inp_{t+1} =====
        float yv[2]; int mv[2], nv[2];
        #pragma unroll
        for (int it = 0; it < 2; it++) {
            int idx = tid + it*NTHREADS;
            int m = idx >> 3, ff = idx & 7;
            float z = fczb[m*F2P + ff] + fcbs[ff];
            float y = ftanh_(0.5f * z);
            g_act[pw][row0+m][HDIM + rk*8 + ff] = __float2half_rn(y);
            yv[it] = y; mv[it] = m; nv[it] = rk*8 + ff;
        }
        __syncthreads();                 // all inp writes done before arrive
        if (more) { bar_arrive(barp); tgt += GCTAS; }   // B: inp published

        // out stores overlap the barrier-B window
        #pragma unroll
        for (int it = 0; it < 2; it++)
            out[(TSTEPS-1-t)*BATCH*IDIM + (row0+mv[it])*IDIM + nv[it]] = yv[it];

        if (more) {
            bar_wait(barp, tgt);         // B
            // ===== phase2: gates(t+1) inp-part; publish gsm =====
            mma_chunks(acc, accfc, &g_act[pw][0][0], Ast, Wsm, row0, wr, wc, lrow, lseg,
                       HCHUNK, NCHUNK, false, 0);
            #pragma unroll
            for (int i = 0; i < 2; i++)
                #pragma unroll
                for (int j = 0; j < 2; j++)
                    wmma::store_matrix_sync(&gsm[(wr*32 + i*16)*GPAD + wc*32 + j*16],
                                            acc[i][j], GPAD, wmma::mem_row_major);
            __syncthreads();
        }
    }
}

extern "C" void kernel_launch(void* const* d_in, const int* in_sizes, int n_in,
                              void* d_out, int out_size)
{
    const float* x    = (const float*)d_in[0];
    // d_in[1] = enc_hiddens : unused by the reference recursion
    const float* h0   = (const float*)d_in[2];
    const float* c0   = (const float*)d_in[3];
    const float* W_ih = (const float*)d_in[4];
    const float* W_hh = (const float*)d_in[5];
    const float* b_ih = (const float*)d_in[6];
    const float* b_hh = (const float*)d_in[7];
    const float* fc_W = (const float*)d_in[8];
    const float* fc_b = (const float*)d_in[9];
    float* out = (float*)d_out;

    cudaFuncSetAttribute(decoder_kernel, cudaFuncAttributeMaxDynamicSharedMemorySize, SMEM_BYTES);

    // Reset group-barrier counters every replay (captured memset node)
    void* barp = nullptr;
    cudaGetSymbolAddress(&barp, g_bar);
    cudaMemsetAsync(barp, 0, sizeof(unsigned) * NGROUPS);

    decoder_kernel<<<NCTA, NTHREADS, SMEM_BYTES>>>(x, h0, c0, W_ih, W_hh,
                                                   b_ih, b_hh, fc_W, fc_b, out);
}

// round 15
// speedup vs baseline: 2.8279x; 1.3765x over previous
#include <cuda_runtime.h>
#include <cuda_fp16.h>
#include <mma.h>
#include <cstdint>
#include <math.h>

using namespace nvcuda;

// Problem constants
#define TSTEPS 512
#define BATCH  512
#define IDIM   128
#define HDIM   512
#define KACT   640   // reordered: cols [0,512)=h, [512,640)=inp

// Partitioning: 8 batch-groups x 16 CTAs = 128 CTAs (1 per SM, one wave)
#define NGROUPS 8
#define GCTAS   16
#define NCTA    (NGROUPS*GCTAS)
#define MB      64
#define HS      32
#define NTHREADS 256   // 8 warps: 2 warp-rows x 4 warp-cols (32x32 gate tiles)

// Extended N: 128 gate cols + 16 fc cols (8 real + 8 zero-pad)
#define NROWS 144

// SMEM padding / tiling
#define WPAD 648      // weight row stride (halfs)
#define GPAD 132      // gates staging row stride (floats)
#define APAD 136      // A-stage row stride (halfs)
#define CHUNK 128     // K columns per staged chunk
#define NCHUNK 5      // 640 / 128
#define HCHUNK 4      // chunks [0,4) = h region [0,512); chunk 4 = inp [512,640)
#define F2P  18       // fcz buffer pitch (floats)

// SMEM layout (bytes):
//  Wsm  144*WPAD*2 = 186624   @ 0        (rows 0..127 gates, 128..143 fc+zeropad)
//  R    max(Ast 2*64*APAD*2=34816, gsm 64*GPAD*4=33792) = 34816 @ 186624 (aliased)
//  fczb 64*F2P*4   = 4608     @ 221440
//  bsm  128*4      = 512      @ 226048
//  fcbs 8*4        = 32       @ 226560
#define SMEM_BYTES 226816

// Global state
__device__ __align__(16) __half g_act[2][BATCH][KACT];   // [parity][row][col]
__device__ unsigned g_bar[NGROUPS];                       // monotonic barrier counters

// ---------------- barriers (release-atomic + relaxed spin, tid0 only) ----------------
__device__ __forceinline__ void bar_arrive(const unsigned* barp) {
    if (threadIdx.x == 0) {
        asm volatile("red.release.gpu.global.add.u32 [%0], %1;"
                     :: "l"(barp), "r"(1u) : "memory");
    }
}
__device__ __forceinline__ void bar_wait(const unsigned* barp, unsigned target) {
    if (threadIdx.x == 0) {
        unsigned v;
        do {
            asm volatile("ld.relaxed.gpu.global.u32 %0, [%1];" : "=r"(v) : "l"(barp));
        } while (v < target);
        asm volatile("fence.acq_rel.gpu;" ::: "memory");
    }
    __syncthreads();
}

__device__ __forceinline__ uint4 ldcg4(const void* p) {
    return __ldcg(reinterpret_cast<const uint4*>(p));
}

// Overflow-safe fast sigmoid/tanh (EX2+RCP MUFU path, rel err ~2^-21)
__device__ __forceinline__ float fsigmoid(float z) {
    float e = __expf(-fabsf(z));
    float num = (z >= 0.f) ? 1.f : e;
    return __fdividef(num, 1.f + e);
}
__device__ __forceinline__ float ftanh_(float z) {
    float e = __expf(-2.f * fabsf(z));
    float r = __fdividef(1.f - e, 1.f + e);
    return (z >= 0.f) ? r : -r;
}

// Staged-chunk MMA over chunks [c_begin, c_end). Accumulates act @ W^T.
// 8 warps: warp (wr,wc) owns rows [wr*32,+32) x gate cols [wc*32,+32).
// fc warps (wids 0,1,6,7; one per SMSP) each accumulate one 16x16 fc band,
// reusing an A fragment they already hold (BRANCHED pick -- no dynamic indexing).
// Staging: LDG(.cg)->reg->STS (proven fastest path; cp.async is issue-bound).
__device__ __forceinline__ void mma_chunks(
    wmma::fragment<wmma::accumulator, 16, 16, 16, float> (&acc)[2][2],
    wmma::fragment<wmma::accumulator, 16, 16, 16, float>& accfc,
    const __half* __restrict__ gact_p,
    __half* __restrict__ Ast,            // [2 buf][64][APAD]
    const __half* __restrict__ Wsm,
    int row0, int wr, int wc, int lrow, int lseg,
    int c_begin, int c_end, bool do_fc, int afsel)
{
    const __half* src = gact_p + (size_t)(row0 + lrow) * KACT + lseg*32;

    // stage chunk c_begin into buf 0 (32 halves = 4 x uint4)
    {
        const __half* s = src + c_begin*CHUNK;
        uint4 v0 = ldcg4(s);
        uint4 v1 = ldcg4(s + 8);
        uint4 v2 = ldcg4(s + 16);
        uint4 v3 = ldcg4(s + 24);
        uint4* d = reinterpret_cast<uint4*>(Ast + lrow*APAD + lseg*32);
        d[0] = v0; d[1] = v1; d[2] = v2; d[3] = v3;
    }
    __syncthreads();

    int buf = 0;
    for (int cc = c_begin; cc < c_end; cc++) {
        uint4 p0, p1, p2, p3;
        const bool hn = (cc + 1 < c_end);
        if (hn) {
            const __half* s = src + (cc+1)*CHUNK;
            p0 = ldcg4(s);
            p1 = ldcg4(s + 8);
            p2 = ldcg4(s + 16);
            p3 = ldcg4(s + 24);
        }

        const __half* Ab = Ast + buf * (64 * APAD);
        const int kbase = cc * CHUNK;
        #pragma unroll
        for (int kt = 0; kt < 8; kt++) {
            wmma::fragment<wmma::matrix_a, 16, 16, 16, __half, wmma::row_major> af[2];
            #pragma unroll
            for (int i = 0; i < 2; i++)
                wmma::load_matrix_sync(af[i], Ab + (wr*32 + i*16)*APAD + kt*16, APAD);
            #pragma unroll
            for (int j = 0; j < 2; j++) {
                wmma::fragment<wmma::matrix_b, 16, 16, 16, __half, wmma::col_major> bf;
                wmma::load_matrix_sync(bf, Wsm + (wc*32 + j*16)*WPAD + kbase + kt*16, WPAD);
                #pragma unroll
                for (int i = 0; i < 2; i++)
                    wmma::mma_sync(acc[i][j], af[i], bf, acc[i][j]);
            }
            if (do_fc) {
                wmma::fragment<wmma::matrix_b, 16, 16, 16, __half, wmma::col_major> bffc;
                wmma::load_matrix_sync(bffc, Wsm + 128*WPAD + kbase + kt*16, WPAD);
                if (afsel) wmma::mma_sync(accfc, af[1], bffc, accfc);
                else       wmma::mma_sync(accfc, af[0], bffc, accfc);
            }
        }
        if (hn) {
            buf ^= 1;
            uint4* d = reinterpret_cast<uint4*>(Ast + buf*(64*APAD) + lrow*APAD + lseg*32);
            d[0] = p0; d[1] = p1; d[2] = p2; d[3] = p3;
        }
        __syncthreads();
    }
}

__global__ void __launch_bounds__(NTHREADS, 1)
decoder_kernel(
    const float* __restrict__ x,    const float* __restrict__ h0,
    const float* __restrict__ c0,   const float* __restrict__ W_ih,
    const float* __restrict__ W_hh, const float* __restrict__ b_ih,
    const float* __restrict__ b_hh, const float* __restrict__ fc_W,
    const float* __restrict__ fc_b, float* __restrict__ out)
{
    extern __shared__ unsigned char smem_raw[];
    __half* Wsm  = (__half*)smem_raw;                        // [144][WPAD]
    __half* Ast  = (__half*)(smem_raw + 186624);             // R: [2][64][APAD]
    float*  gsm  = (float*)(smem_raw + 186624);              // R: [64][GPAD] (aliased)
    float*  fczb = (float*)(smem_raw + 221440);              // [64][F2P]
    float*  bsm  = (float*)(smem_raw + 226048);              // [128]
    float*  fcbs = (float*)(smem_raw + 226560);              // [8]

    const int tid  = threadIdx.x;
    const int gid  = blockIdx.x / GCTAS;
    const int rk   = blockIdx.x % GCTAS;
    const int row0 = gid * MB;
    const int hs   = rk * HS;
    const unsigned* barp = &g_bar[gid];

    const int wid = tid >> 5;
    const int wr  = wid >> 2;        // 0..1 : 32 gate rows (batch m) each
    const int wc  = wid & 3;         // 0..3 : 32 gate cols each
    const int lrow = tid >> 2;       // 0..63
    const int lseg = tid & 3;        // 0..3
    // fc spread: wids 0,1 (wr=0, SMSP0/1) and 6,7 (wr=1, SMSP2/3); one 16-row band each.
    const bool fcw = (wid == 0) || (wid == 1) || (wid == 6) || (wid == 7);
    const int fcband = (wid >= 4) ? (wid - 4) : wid;   // 0,1,2,3
    const int afsel  = fcband & 1;                      // band rows == wr*32 + afsel*16

    // ---------------- init (once) ----------------
    // Wsm rows 0..127: gates, K-reordered (k<512 -> W_hh, k>=512 -> W_ih)
    // Wsm rows 128..143: fc rows (8 real over K<512, rest zero)
    for (int idx = tid; idx < NROWS*KACT; idx += NTHREADS) {
        int r = idx / KACT, k = idx - r*KACT;
        float v;
        if (r < 128) {
            int q = r >> 5, j = r & 31;
            int grow = q*HDIM + hs + j;
            v = (k < HDIM) ? W_hh[grow*HDIM + k] : W_ih[grow*IDIM + (k - HDIM)];
        } else {
            int ff = r - 128;
            v = (ff < 8 && k < HDIM) ? fc_W[(rk*8 + ff)*HDIM + k] : 0.0f;
        }
        Wsm[r*WPAD + k] = __float2half_rn(v);
    }
    for (int r = tid; r < 128; r += NTHREADS) {
        int q = r >> 5, j = r & 31;
        bsm[r] = b_ih[q*HDIM + hs + j] + b_hh[q*HDIM + hs + j];
    }
    if (tid < 8) fcbs[tid] = fc_b[rk*8 + tid];

    // cell state in registers: element it -> (m = (tid>>5)+it*8, j = tid&31)
    float cr[8];
    #pragma unroll
    for (int it = 0; it < 8; it++) {
        int m = (tid >> 5) + it*8, j = tid & 31;
        cr[it] = c0[(row0+m)*HDIM + hs + j];
    }

    // seed g_act parity 0: h at cols [hs,hs+32), inp at cols [512+rk*8,+8)
    for (int idx = tid; idx < MB*HS; idx += NTHREADS) {
        int m = idx >> 5, j = idx & 31;
        g_act[0][row0+m][hs+j] = __float2half_rn(h0[(row0+m)*HDIM + hs + j]);
    }
    for (int idx = tid; idx < MB*8; idx += NTHREADS) {
        int m = idx >> 3, ccol = rk*8 + (idx & 7);
        g_act[0][row0+m][HDIM+ccol] =
            __float2half_rn(x[(TSTEPS-1)*BATCH*IDIM + (row0+m)*IDIM + ccol]);
    }

    __syncthreads();              // all seed writes done before arrive
    bar_arrive(barp);
    unsigned tgt = GCTAS;
    bar_wait(barp, tgt);          // seeds visible group-wide

    wmma::fragment<wmma::accumulator, 16, 16, 16, float> acc[2][2];
    wmma::fragment<wmma::accumulator, 16, 16, 16, float> accfc;

    // ---------------- prologue: gates(0) (no fc) ----------------
    {
        #pragma unroll
        for (int i = 0; i < 2; i++)
            #pragma unroll
            for (int j = 0; j < 2; j++)
                wmma::fill_fragment(acc[i][j], 0.0f);
        mma_chunks(acc, accfc, &g_act[0][0][0], Ast, Wsm, row0, wr, wc, lrow, lseg,
                   0, NCHUNK, false, 0);
        #pragma unroll
        for (int i = 0; i < 2; i++)
            #pragma unroll
            for (int j = 0; j < 2; j++)
                wmma::store_matrix_sync(&gsm[(wr*32 + i*16)*GPAD + wc*32 + j*16],
                                        acc[i][j], GPAD, wmma::mem_row_major);
        __syncthreads();
    }

    // ---------------- 512 sequential steps ----------------
    for (int t = 0; t < TSTEPS; t++) {
        const int pw = (t + 1) & 1;      // parity holding h_{t+1} / inp_{t+1}
        const bool more = (t < TSTEPS - 1);

        // ===== pointwise LSTM: gsm (gates_t) + cr -> h_{t+1} (global pw) =====
        #pragma unroll
        for (int it = 0; it < 8; it++) {
            int m = (tid >> 5) + it*8, j = tid & 31;
            float zi = gsm[m*GPAD +      j] + bsm[     j];
            float zf = gsm[m*GPAD + 32 + j] + bsm[32 + j];
            float zg = gsm[m*GPAD + 64 + j] + bsm[64 + j];
            float zo = gsm[m*GPAD + 96 + j] + bsm[96 + j];
            float ig = fsigmoid(zi);
            float fg = fsigmoid(zf);
            float gg = ftanh_(zg);
            float og = fsigmoid(zo);
            float cn = fg*cr[it] + ig*gg;
            float hn = og * ftanh_(cn);
            cr[it] = cn;
            g_act[pw][row0+m][hs+j] = __float2half_rn(hn);
        }
        __syncthreads();                 // all h writes done before arrive
        bar_arrive(barp);                // A: h_{t+1} published
        tgt += GCTAS;
        bar_wait(barp, tgt);

        // ===== phase1: gates(t+1) h-part + FULL fcz_t (fc on 4 warps) =====
        #pragma unroll
        for (int i = 0; i < 2; i++)
            #pragma unroll
            for (int j = 0; j < 2; j++)
                wmma::fill_fragment(acc[i][j], 0.0f);
        wmma::fill_fragment(accfc, 0.0f);
        mma_chunks(acc, accfc, &g_act[pw][0][0], Ast, Wsm, row0, wr, wc, lrow, lseg,
                   0, HCHUNK, fcw, afsel);
        if (fcw)
            wmma::store_matrix_sync(&fczb[fcband*16*F2P], accfc, F2P, wmma::mem_row_major);
        __syncthreads();

        // ===== finalize: out_t = tanh(0.5*(fcz+b)); feedback inp_{t+1} =====
        float yv[2]; int mv[2], nv[2];
        #pragma unroll
        for (int it = 0; it < 2; it++) {
            int idx = tid + it*NTHREADS;
            int m = idx >> 3, ff = idx & 7;
            float z = fczb[m*F2P + ff] + fcbs[ff];
            float y = ftanh_(0.5f * z);
            g_act[pw][row0+m][HDIM + rk*8 + ff] = __float2half_rn(y);
            yv[it] = y; mv[it] = m; nv[it] = rk*8 + ff;
        }
        __syncthreads();                 // all inp writes done before arrive
        if (more) { bar_arrive(barp); tgt += GCTAS; }   // B: inp published

        // out stores overlap the barrier-B window
        #pragma unroll
        for (int it = 0; it < 2; it++)
            out[(TSTEPS-1-t)*BATCH*IDIM + (row0+mv[it])*IDIM + nv[it]] = yv[it];

        if (more) {
            bar_wait(barp, tgt);         // B
            // ===== phase2: gates(t+1) inp-part; publish gsm =====
            mma_chunks(acc, accfc, &g_act[pw][0][0], Ast, Wsm, row0, wr, wc, lrow, lseg,
                       HCHUNK, NCHUNK, false, 0);
            #pragma unroll
            for (int i = 0; i < 2; i++)
                #pragma unroll
                for (int j = 0; j < 2; j++)
                    wmma::store_matrix_sync(&gsm[(wr*32 + i*16)*GPAD + wc*32 + j*16],
                                            acc[i][j], GPAD, wmma::mem_row_major);
            __syncthreads();
        }
    }
}

extern "C" void kernel_launch(void* const* d_in, const int* in_sizes, int n_in,
                              void* d_out, int out_size)
{
    const float* x    = (const float*)d_in[0];
    // d_in[1] = enc_hiddens : unused by the reference recursion
    const float* h0   = (const float*)d_in[2];
    const float* c0   = (const float*)d_in[3];
    const float* W_ih = (const float*)d_in[4];
    const float* W_hh = (const float*)d_in[5];
    const float* b_ih = (const float*)d_in[6];
    const float* b_hh = (const float*)d_in[7];
    const float* fc_W = (const float*)d_in[8];
    const float* fc_b = (const float*)d_in[9];
    float* out = (float*)d_out;

    cudaFuncSetAttribute(decoder_kernel, cudaFuncAttributeMaxDynamicSharedMemorySize, SMEM_BYTES);

    // Reset group-barrier counters every replay (captured memset node)
    void* barp = nullptr;
    cudaGetSymbolAddress(&barp, g_bar);
    cudaMemsetAsync(barp, 0, sizeof(unsigned) * NGROUPS);

    decoder_kernel<<<NCTA, NTHREADS, SMEM_BYTES>>>(x, h0, c0, W_ih, W_hh,
                                                   b_ih, b_hh, fc_W, fc_b, out);
}

// round 16
// speedup vs baseline: 3.1674x; 1.1201x over previous
#include <cuda_runtime.h>
#include <cuda_fp16.h>
#include <mma.h>
#include <cstdint>
#include <math.h>

using namespace nvcuda;

// Problem constants
#define TSTEPS 512
#define BATCH  512
#define IDIM   128
#define HDIM   512
#define KACT   640   // reordered: cols [0,512)=h, [512,640)=inp

// Partitioning: 8 batch-groups x 16 CTAs = 128 CTAs (1 per SM, one wave)
#define NGROUPS 8
#define GCTAS   16
#define NCTA    (NGROUPS*GCTAS)
#define MB      64
#define HS      32
#define NTHREADS 256   // 8 warps: 2 warp-rows x 4 warp-cols (32x32 gate tiles)

// Extended N: 128 gate cols + 16 fc cols (8 real + 8 zero-pad)
#define NROWS 144

// SMEM padding / tiling
#define WPAD 648      // weight row stride (halfs)
#define GPAD 132      // gates staging row stride (floats)
#define APAD 136      // A-stage row stride (halfs)
#define CHUNK 128     // K columns per staged chunk
#define NCHUNK 5      // 640 / 128
#define HCHUNK 4      // chunks [0,4) = h region [0,512); chunk 4 = inp [512,640)
#define F2P  18       // fcz buffer pitch (floats)

// SMEM layout (bytes):
//  Wsm  144*WPAD*2 = 186624   @ 0        (rows 0..127 gates, 128..143 fc+zeropad)
//  R    max(Ast 2*64*APAD*2=34816, gsm 64*GPAD*4=33792) = 34816 @ 186624 (aliased)
//  fczb 64*F2P*4   = 4608     @ 221440
//  bsm  128*4      = 512      @ 226048
//  fcbs 8*4        = 32       @ 226560
#define SMEM_BYTES 226816

// Global state
__device__ __align__(16) __half g_act[2][BATCH][KACT];   // [parity][row][col]
__device__ unsigned g_bar[NGROUPS];                       // monotonic barrier counters

// ---------------- barriers (release-atomic + relaxed spin, tid0 only) ----------------
__device__ __forceinline__ void bar_arrive(const unsigned* barp) {
    if (threadIdx.x == 0) {
        asm volatile("red.release.gpu.global.add.u32 [%0], %1;"
                     :: "l"(barp), "r"(1u) : "memory");
    }
}
__device__ __forceinline__ void bar_wait(const unsigned* barp, unsigned target) {
    if (threadIdx.x == 0) {
        unsigned v;
        do {
            asm volatile("ld.relaxed.gpu.global.u32 %0, [%1];" : "=r"(v) : "l"(barp));
        } while (v < target);
        asm volatile("fence.acq_rel.gpu;" ::: "memory");
    }
    __syncthreads();
}

__device__ __forceinline__ uint4 ldcg4(const void* p) {
    return __ldcg(reinterpret_cast<const uint4*>(p));
}

// MUFU.TANH-based activations: 1 MUFU/op vs 2 (EX2+RCP) for the exp path.
// tanh.approx.f32 abs err ~2^-11 -- same scale as the fp16 h rounding already
// present per step, which measurably does not compound.
__device__ __forceinline__ float ftanh_(float z) {
    float r;
    asm("tanh.approx.f32 %0, %1;" : "=f"(r) : "f"(z));
    return r;
}
__device__ __forceinline__ float fsigmoid(float z) {
    return fmaf(0.5f, ftanh_(0.5f * z), 0.5f);
}

// Staged-chunk MMA over chunks [c_begin, c_end). Accumulates act @ W^T.
// 8 warps: warp (wr,wc) owns rows [wr*32,+32) x gate cols [wc*32,+32).
// do_fc warps (wids 3,4 -- r10-proven) accumulate the 16-col fc tile with both
// A fragments (accfc[2]); no dynamic fragment indexing anywhere.
// Staging: LDG(.cg)->reg->STS, 4x uint4 per thread per chunk (proven fastest).
__device__ __forceinline__ void mma_chunks(
    wmma::fragment<wmma::accumulator, 16, 16, 16, float> (&acc)[2][2],
    wmma::fragment<wmma::accumulator, 16, 16, 16, float> (&accfc)[2],
    const __half* __restrict__ gact_p,
    __half* __restrict__ Ast,            // [2 buf][64][APAD]
    const __half* __restrict__ Wsm,
    int row0, int wr, int wc, int lrow, int lseg,
    int c_begin, int c_end, bool do_fc)
{
    const __half* src = gact_p + (size_t)(row0 + lrow) * KACT + lseg*32;

    // stage chunk c_begin into buf 0 (32 halves = 4 x uint4)
    {
        const __half* s = src + c_begin*CHUNK;
        uint4 v0 = ldcg4(s);
        uint4 v1 = ldcg4(s + 8);
        uint4 v2 = ldcg4(s + 16);
        uint4 v3 = ldcg4(s + 24);
        uint4* d = reinterpret_cast<uint4*>(Ast + lrow*APAD + lseg*32);
        d[0] = v0; d[1] = v1; d[2] = v2; d[3] = v3;
    }
    __syncthreads();

    int buf = 0;
    for (int cc = c_begin; cc < c_end; cc++) {
        uint4 p0, p1, p2, p3;
        const bool hn = (cc + 1 < c_end);
        if (hn) {
            const __half* s = src + (cc+1)*CHUNK;
            p0 = ldcg4(s);
            p1 = ldcg4(s + 8);
            p2 = ldcg4(s + 16);
            p3 = ldcg4(s + 24);
        }

        const __half* Ab = Ast + buf * (64 * APAD);
        const int kbase = cc * CHUNK;
        #pragma unroll
        for (int kt = 0; kt < 8; kt++) {
            wmma::fragment<wmma::matrix_a, 16, 16, 16, __half, wmma::row_major> af[2];
            #pragma unroll
            for (int i = 0; i < 2; i++)
                wmma::load_matrix_sync(af[i], Ab + (wr*32 + i*16)*APAD + kt*16, APAD);
            #pragma unroll
            for (int j = 0; j < 2; j++) {
                wmma::fragment<wmma::matrix_b, 16, 16, 16, __half, wmma::col_major> bf;
                wmma::load_matrix_sync(bf, Wsm + (wc*32 + j*16)*WPAD + kbase + kt*16, WPAD);
                #pragma unroll
                for (int i = 0; i < 2; i++)
                    wmma::mma_sync(acc[i][j], af[i], bf, acc[i][j]);
            }
            if (do_fc) {
                wmma::fragment<wmma::matrix_b, 16, 16, 16, __half, wmma::col_major> bffc;
                wmma::load_matrix_sync(bffc, Wsm + 128*WPAD + kbase + kt*16, WPAD);
                #pragma unroll
                for (int i = 0; i < 2; i++)
                    wmma::mma_sync(accfc[i], af[i], bffc, accfc[i]);
            }
        }
        if (hn) {
            buf ^= 1;
            uint4* d = reinterpret_cast<uint4*>(Ast + buf*(64*APAD) + lrow*APAD + lseg*32);
            d[0] = p0; d[1] = p1; d[2] = p2; d[3] = p3;
        }
        __syncthreads();
    }
}

__global__ void __launch_bounds__(NTHREADS, 1)
decoder_kernel(
    const float* __restrict__ x,    const float* __restrict__ h0,
    const float* __restrict__ c0,   const float* __restrict__ W_ih,
    const float* __restrict__ W_hh, const float* __restrict__ b_ih,
    const float* __restrict__ b_hh, const float* __restrict__ fc_W,
    const float* __restrict__ fc_b, float* __restrict__ out)
{
    extern __shared__ unsigned char smem_raw[];
    __half* Wsm  = (__half*)smem_raw;                        // [144][WPAD]
    __half* Ast  = (__half*)(smem_raw + 186624);             // R: [2][64][APAD]
    float*  gsm  = (float*)(smem_raw + 186624);              // R: [64][GPAD] (aliased)
    float*  fczb = (float*)(smem_raw + 221440);              // [64][F2P]
    float*  bsm  = (float*)(smem_raw + 226048);              // [128]
    float*  fcbs = (float*)(smem_raw + 226560);              // [8]

    const int tid  = threadIdx.x;
    const int gid  = blockIdx.x / GCTAS;
    const int rk   = blockIdx.x % GCTAS;
    const int row0 = gid * MB;
    const int hs   = rk * HS;
    const unsigned* barp = &g_bar[gid];

    const int wid = tid >> 5;
    const int wr  = wid >> 2;        // 0..1 : 32 gate rows (batch m) each
    const int wc  = wid & 3;         // 0..3 : 32 gate cols each
    const int lrow = tid >> 2;       // 0..63
    const int lseg = tid & 3;        // 0..3
    // fc tile carried by wids 3 (SMSP3, wr=0) and 4 (SMSP0, wr=1) -- r10-proven
    const bool fcw = (wid == 3) || (wid == 4);

    // ---------------- init (once) ----------------
    // Wsm rows 0..127: gates, K-reordered (k<512 -> W_hh, k>=512 -> W_ih)
    // Wsm rows 128..143: fc rows (8 real over K<512, rest zero)
    for (int idx = tid; idx < NROWS*KACT; idx += NTHREADS) {
        int r = idx / KACT, k = idx - r*KACT;
        float v;
        if (r < 128) {
            int q = r >> 5, j = r & 31;
            int grow = q*HDIM + hs + j;
            v = (k < HDIM) ? W_hh[grow*HDIM + k] : W_ih[grow*IDIM + (k - HDIM)];
        } else {
            int ff = r - 128;
            v = (ff < 8 && k < HDIM) ? fc_W[(rk*8 + ff)*HDIM + k] : 0.0f;
        }
        Wsm[r*WPAD + k] = __float2half_rn(v);
    }
    for (int r = tid; r < 128; r += NTHREADS) {
        int q = r >> 5, j = r & 31;
        bsm[r] = b_ih[q*HDIM + hs + j] + b_hh[q*HDIM + hs + j];
    }
    if (tid < 8) fcbs[tid] = fc_b[rk*8 + tid];

    // cell state in registers: element it -> (m = (tid>>5)+it*8, j = tid&31)
    float cr[8];
    #pragma unroll
    for (int it = 0; it < 8; it++) {
        int m = (tid >> 5) + it*8, j = tid & 31;
        cr[it] = c0[(row0+m)*HDIM + hs + j];
    }

    // seed g_act parity 0: h at cols [hs,hs+32), inp at cols [512+rk*8,+8)
    for (int idx = tid; idx < MB*HS; idx += NTHREADS) {
        int m = idx >> 5, j = idx & 31;
        g_act[0][row0+m][hs+j] = __float2half_rn(h0[(row0+m)*HDIM + hs + j]);
    }
    for (int idx = tid; idx < MB*8; idx += NTHREADS) {
        int m = idx >> 3, ccol = rk*8 + (idx & 7);
        g_act[0][row0+m][HDIM+ccol] =
            __float2half_rn(x[(TSTEPS-1)*BATCH*IDIM + (row0+m)*IDIM + ccol]);
    }

    __syncthreads();              // all seed writes done before arrive
    bar_arrive(barp);
    unsigned tgt = GCTAS;
    bar_wait(barp, tgt);          // seeds visible group-wide

    wmma::fragment<wmma::accumulator, 16, 16, 16, float> acc[2][2];
    wmma::fragment<wmma::accumulator, 16, 16, 16, float> accfc[2];

    // ---------------- prologue: gates(0) (no fc) ----------------
    {
        #pragma unroll
        for (int i = 0; i < 2; i++)
            #pragma unroll
            for (int j = 0; j < 2; j++)
                wmma::fill_fragment(acc[i][j], 0.0f);
        mma_chunks(acc, accfc, &g_act[0][0][0], Ast, Wsm, row0, wr, wc, lrow, lseg,
                   0, NCHUNK, false);
        #pragma unroll
        for (int i = 0; i < 2; i++)
            #pragma unroll
            for (int j = 0; j < 2; j++)
                wmma::store_matrix_sync(&gsm[(wr*32 + i*16)*GPAD + wc*32 + j*16],
                                        acc[i][j], GPAD, wmma::mem_row_major);
        __syncthreads();
    }

    // ---------------- 512 sequential steps ----------------
    for (int t = 0; t < TSTEPS; t++) {
        const int pw = (t + 1) & 1;      // parity holding h_{t+1} / inp_{t+1}
        const bool more = (t < TSTEPS - 1);

        // ===== pointwise LSTM: gsm (gates_t) + cr -> h_{t+1} (global pw) =====
        #pragma unroll
        for (int it = 0; it < 8; it++) {
            int m = (tid >> 5) + it*8, j = tid & 31;
            float zi = gsm[m*GPAD +      j] + bsm[     j];
            float zf = gsm[m*GPAD + 32 + j] + bsm[32 + j];
            float zg = gsm[m*GPAD + 64 + j] + bsm[64 + j];
            float zo = gsm[m*GPAD + 96 + j] + bsm[96 + j];
            float ig = fsigmoid(zi);
            float fg = fsigmoid(zf);
            float gg = ftanh_(zg);
            float og = fsigmoid(zo);
            float cn = fg*cr[it] + ig*gg;
            float hn = og * ftanh_(cn);
            cr[it] = cn;
            g_act[pw][row0+m][hs+j] = __float2half_rn(hn);
        }
        __syncthreads();                 // all h writes done before arrive
        bar_arrive(barp);                // A: h_{t+1} published
        tgt += GCTAS;
        bar_wait(barp, tgt);

        // ===== phase1: gates(t+1) h-part + FULL fcz_t (fc on wids 3,4) =====
        #pragma unroll
        for (int i = 0; i < 2; i++) {
            wmma::fill_fragment(accfc[i], 0.0f);
            #pragma unroll
            for (int j = 0; j < 2; j++)
                wmma::fill_fragment(acc[i][j], 0.0f);
        }
        mma_chunks(acc, accfc, &g_act[pw][0][0], Ast, Wsm, row0, wr, wc, lrow, lseg,
                   0, HCHUNK, fcw);
        if (fcw) {
            #pragma unroll
            for (int i = 0; i < 2; i++)
                wmma::store_matrix_sync(&fczb[(wr*32 + i*16)*F2P], accfc[i],
                                        F2P, wmma::mem_row_major);
        }
        __syncthreads();

        // ===== finalize: out_t = tanh(0.5*(fcz+b)); feedback inp_{t+1} =====
        float yv[2]; int mv[2], nv[2];
        #pragma unroll
        for (int it = 0; it < 2; it++) {
            int idx = tid + it*NTHREADS;
            int m = idx >> 3, ff = idx & 7;
            float z = fczb[m*F2P + ff] + fcbs[ff];
            float y = ftanh_(0.5f * z);  // == 2*sigmoid(z) - 1
            g_act[pw][row0+m][HDIM + rk*8 + ff] = __float2half_rn(y);
            yv[it] = y; mv[it] = m; nv[it] = rk*8 + ff;
        }
        __syncthreads();                 // all inp writes done before arrive
        if (more) { bar_arrive(barp); tgt += GCTAS; }   // B: inp published

        // out stores overlap the barrier-B window
        #pragma unroll
        for (int it = 0; it < 2; it++)
            out[(TSTEPS-1-t)*BATCH*IDIM + (row0+mv[it])*IDIM + nv[it]] = yv[it];

        if (more) {
            bar_wait(barp, tgt);         // B
            // ===== phase2: gates(t+1) inp-part; publish gsm =====
            mma_chunks(acc, accfc, &g_act[pw][0][0], Ast, Wsm, row0, wr, wc, lrow, lseg,
                       HCHUNK, NCHUNK, false);
            #pragma unroll
            for (int i = 0; i < 2; i++)
                #pragma unroll
                for (int j = 0; j < 2; j++)
                    wmma::store_matrix_sync(&gsm[(wr*32 + i*16)*GPAD + wc*32 + j*16],
                                            acc[i][j], GPAD, wmma::mem_row_major);
            __syncthreads();
        }
    }
}

extern "C" void kernel_launch(void* const* d_in, const int* in_sizes, int n_in,
                              void* d_out, int out_size)
{
    const float* x    = (const float*)d_in[0];
    // d_in[1] = enc_hiddens : unused by the reference recursion
    const float* h0   = (const float*)d_in[2];
    const float* c0   = (const float*)d_in[3];
    const float* W_ih = (const float*)d_in[4];
    const float* W_hh = (const float*)d_in[5];
    const float* b_ih = (const float*)d_in[6];
    const float* b_hh = (const float*)d_in[7];
    const float* fc_W = (const float*)d_in[8];
    const float* fc_b = (const float*)d_in[9];
    float* out = (float*)d_out;

    cudaFuncSetAttribute(decoder_kernel, cudaFuncAttributeMaxDynamicSharedMemorySize, SMEM_BYTES);

    // Reset group-barrier counters every replay (captured memset node)
    void* barp = nullptr;
    cudaGetSymbolAddress(&barp, g_bar);
    cudaMemsetAsync(barp, 0, sizeof(unsigned) * NGROUPS);

    decoder_kernel<<<NCTA, NTHREADS, SMEM_BYTES>>>(x, h0, c0, W_ih, W_hh,
                                                   b_ih, b_hh, fc_W, fc_b, out);
}